// round 7
// baseline (speedup 1.0000x reference)
#include <cuda_runtime.h>
#include <math.h>

// ---------------- scratch (no allocations allowed) ----------------
__device__ float g_Q[2048 * 4096];   // [S, NH*D]
__device__ float g_K[2048 * 1024];   // [S, NKV*D]
__device__ float g_V[2048 * 1024];   // [S, NKV*D]
__device__ float g_A[2048 * 4096];   // attention output [S, NH*D]

// ---------------- naive GEMM: C[M,N] = A[M,K] @ B[K,N], row-major ----------------
// One thread per output element. A[m][k] is uniform across the block (L1/L2
// broadcast); B[k][n] is coalesced across threads. No smem, no vectorization —
// minimal surface for bugs.
__global__ void gemm_naive(const float* __restrict__ A,
                           const float* __restrict__ B,
                           float* __restrict__ C,
                           int M, int N, int K) {
    int n = blockIdx.x * 128 + threadIdx.x;
    int m = blockIdx.y;
    if (n >= N || m >= M) return;
    const float* Arow = A + (size_t)m * K;
    float acc = 0.f;
    for (int k = 0; k < K; k++) {
        acc += Arow[k] * B[(size_t)k * N + n];
    }
    C[(size_t)m * N + n] = acc;
}

// ---------------- RoPE (in-place), restructured math ----------------
// out[i]    = x[i]*cos(a_i)    - x[i+64]*sin(a_i)
// out[i+64] = x[i+64]*cos(a_i) + x[i]*sin(a_i),  a_i = pos * 10000^(-2i/128)
__global__ void rope_naive(float* __restrict__ X, const int* __restrict__ pos_ids, int nh) {
    int idx = blockIdx.x * 256 + threadIdx.x;   // over S * nh * 64
    int total = 2048 * nh * 64;
    if (idx >= total) return;
    int i = idx % 64;
    int h = (idx / 64) % nh;
    int s = idx / (64 * nh);
    // inv_freq = 10000^(-(2i)/128) computed via exp/log (different path than powf)
    const float LN10000 = 9.210340371976184f;
    float inv = __expf(-((float)(2 * i) / 128.0f) * LN10000);
    float ang = (float)pos_ids[s] * inv;
    float c = cosf(ang);
    float sn = sinf(ang);
    float* row = X + (size_t)s * (nh * 128) + h * 128;
    float x1 = row[i];
    float x2 = row[i + 64];
    row[i]      = x1 * c - x2 * sn;
    row[i + 64] = x2 * c + x1 * sn;
}

// ---------------- naive attention: one block per (query row, head) ----------------
// Full score row (<=2048) lives in smem; plain two-pass softmax; no tiling,
// no online rescaling, no causal-tile edge cases: k ranges over [0, q] only.
__global__ __launch_bounds__(128) void attn_naive(const float* __restrict__ Q,
                                                  const float* __restrict__ K,
                                                  const float* __restrict__ V,
                                                  float* __restrict__ O) {
    __shared__ float sc[2048];
    __shared__ float red[128];

    const int q  = blockIdx.x;   // 0..2047
    const int h  = blockIdx.y;   // 0..31
    const int kh = h >> 2;       // GQA: 4 query heads per kv head
    const int t  = threadIdx.x;  // 0..127

    const float scale = 0.08838834764831845f;   // 1/sqrt(128)
    const float* qrow = Q + (size_t)q * 4096 + h * 128;

    // scores for keys k = t, t+128, ... <= q
    float mx = -INFINITY;
    for (int k = t; k <= q; k += 128) {
        const float* krow = K + (size_t)k * 1024 + kh * 128;
        float s = 0.f;
        for (int d = 0; d < 128; d++) s += qrow[d] * krow[d];
        s *= scale;
        sc[k] = s;
        mx = fmaxf(mx, s);
    }
    red[t] = mx;
    __syncthreads();
    for (int off = 64; off > 0; off >>= 1) {
        if (t < off) red[t] = fmaxf(red[t], red[t + off]);
        __syncthreads();
    }
    float m = red[0];
    __syncthreads();

    float sum = 0.f;
    for (int k = t; k <= q; k += 128) {
        float p = __expf(sc[k] - m);
        sc[k] = p;
        sum += p;
    }
    red[t] = sum;
    __syncthreads();
    for (int off = 64; off > 0; off >>= 1) {
        if (t < off) red[t] += red[t + off];
        __syncthreads();
    }
    float invl = 1.f / red[0];

    // output: thread t owns dim d = t (coalesced V reads)
    float acc = 0.f;
    for (int k = 0; k <= q; k++) {
        acc += sc[k] * V[(size_t)k * 1024 + kh * 128 + t];
    }
    O[(size_t)q * 4096 + h * 128 + t] = acc * invl;
}

// ---------------- launch ----------------
extern "C" void kernel_launch(void* const* d_in, const int* in_sizes, int n_in,
                              void* d_out, int out_size) {
    // Size-driven input identification (no-op under dict order; handles
    // name-sorted order too). sizes: hs=8388608, pos=2048, {Wq,Wo}=16777216,
    // {Wk,Wv}=4194304.
    int i16[2] = {-1, -1}, n16 = 0;
    int i4[2]  = {-1, -1}, n4  = 0;
    int iHS = -1, iPOS = -1;
    for (int i = 0; i < 6; i++) {
        int s = in_sizes[i];
        if (s == 16777216)      { if (n16 < 2) i16[n16++] = i; }
        else if (s == 4194304)  { if (n4  < 2) i4[n4++]   = i; }
        else if (s == 8388608)  iHS = i;
        else                    iPOS = i;   // 2048
    }
    int iWq, iWo;
    if (i16[1] == i16[0] + 1) { iWo = i16[0]; iWq = i16[1]; }   // name-sorted: Wo,Wq adjacent
    else                      { iWq = i16[0]; iWo = i16[1]; }   // dict order: Wq ... Wo
    const int iWk = i4[0];
    const int iWv = i4[1];

    const float* hs  = (const float*)d_in[iHS];
    const int*   pos = (const int*)d_in[iPOS];
    const float* Wq  = (const float*)d_in[iWq];
    const float* Wk  = (const float*)d_in[iWk];
    const float* Wv  = (const float*)d_in[iWv];
    const float* Wo  = (const float*)d_in[iWo];
    float* out = (float*)d_out;

    float *Q, *K, *V, *A;
    cudaGetSymbolAddress((void**)&Q, g_Q);
    cudaGetSymbolAddress((void**)&K, g_K);
    cudaGetSymbolAddress((void**)&V, g_V);
    cudaGetSymbolAddress((void**)&A, g_A);

    // QKV projections (naive)
    {
        dim3 gq(4096 / 128, 2048);
        gemm_naive<<<gq, 128>>>(hs, Wq, Q, 2048, 4096, 4096);
        dim3 gkv(1024 / 128, 2048);
        gemm_naive<<<gkv, 128>>>(hs, Wk, K, 2048, 1024, 4096);
        gemm_naive<<<gkv, 128>>>(hs, Wv, V, 2048, 1024, 4096);
    }

    // RoPE on Q (32 heads) and K (8 heads)
    {
        int totq = 2048 * 32 * 64;
        rope_naive<<<(totq + 255) / 256, 256>>>(Q, pos, 32);
        int totk = 2048 * 8 * 64;
        rope_naive<<<(totk + 255) / 256, 256>>>(K, pos, 8);
    }

    // Attention (naive, one block per (q, head))
    {
        dim3 ga(2048, 32);
        attn_naive<<<ga, 128>>>(Q, K, V, A);
    }

    // Output projection (naive)
    {
        dim3 go(4096 / 128, 2048);
        gemm_naive<<<go, 128>>>(A, Wo, out, 2048, 4096, 4096);
    }
}

// round 8
// speedup vs baseline: 1.4816x; 1.4816x over previous
#include <cuda_runtime.h>
#include <math.h>

// ---------------- scratch (no allocations allowed) ----------------
__device__ float g_Q[2048 * 4096];   // [S, NH*D]
__device__ float g_K[2048 * 1024];   // [S, NKV*D]
__device__ float g_V[2048 * 1024];   // [S, NKV*D]
__device__ float g_A[2048 * 4096];   // attention output [S, NH*D]

// ---------------- tiled SGEMM: C[M,N] = A[M,K] @ B[K,N], row-major ----------------
// BM=BN=128, BK=16, 256 threads, 8x8 per thread. Index algebra verified:
//   As[kk][row] = A[bm+row][k0+kk],  Bs[kk][col] = B[k0+kk][bn+col]
//   acc[i][j] = sum_k A[bm+tm0+i][k] * B[k][bn+tn0+j] -> C[bm+tm0+i][bn+tn0+j]
#define BM 128
#define BN 128
#define BKK 16

__global__ __launch_bounds__(256) void sgemm_kernel(const float* __restrict__ A,
                                                    const float* __restrict__ B,
                                                    float* __restrict__ C,
                                                    int M, int N, int K) {
    __shared__ float As[BKK][BM + 4];
    __shared__ float Bs[BKK][BN + 4];

    const int bm = blockIdx.y * BM;
    const int bn = blockIdx.x * BN;
    const int t = threadIdx.x;
    const int tm0 = (t >> 4) * 8;
    const int tn0 = (t & 15) * 8;

    float acc[8][8];
#pragma unroll
    for (int i = 0; i < 8; i++)
#pragma unroll
        for (int j = 0; j < 8; j++) acc[i][j] = 0.f;

    const float* Ab = A + (size_t)bm * K;
    const float* Bb = B + bn;

    for (int k0 = 0; k0 < K; k0 += BKK) {
        // A tile: 128 rows x 16 cols, stored transposed As[k][m]
#pragma unroll
        for (int i = 0; i < 2; i++) {
            int idx = t + i * 256;          // 0..511 = row*4 + c4
            int row = idx >> 2;             // 0..127
            int c4  = idx & 3;              // 0..3
            float4 v = *(const float4*)(Ab + (size_t)row * K + k0 + c4 * 4);
            As[c4 * 4 + 0][row] = v.x;
            As[c4 * 4 + 1][row] = v.y;
            As[c4 * 4 + 2][row] = v.z;
            As[c4 * 4 + 3][row] = v.w;
        }
        // B tile: 16 rows x 128 cols
#pragma unroll
        for (int i = 0; i < 2; i++) {
            int idx = t + i * 256;          // 0..511 = row*32 + c4
            int row = idx >> 5;             // 0..15
            int c4  = idx & 31;             // 0..31
            *(float4*)&Bs[row][c4 * 4] =
                *(const float4*)(Bb + (size_t)(k0 + row) * N + c4 * 4);
        }
        __syncthreads();

#pragma unroll
        for (int k = 0; k < BKK; k++) {
            float a[8], b[8];
#pragma unroll
            for (int x = 0; x < 8; x++) a[x] = As[k][tm0 + x];
#pragma unroll
            for (int x = 0; x < 8; x++) b[x] = Bs[k][tn0 + x];
#pragma unroll
            for (int i = 0; i < 8; i++)
#pragma unroll
                for (int j = 0; j < 8; j++) acc[i][j] += a[i] * b[j];
        }
        __syncthreads();
    }

#pragma unroll
    for (int i = 0; i < 8; i++) {
        float4 v0 = make_float4(acc[i][0], acc[i][1], acc[i][2], acc[i][3]);
        float4 v1 = make_float4(acc[i][4], acc[i][5], acc[i][6], acc[i][7]);
        size_t base = (size_t)(bm + tm0 + i) * N + bn + tn0;
        *(float4*)&C[base]     = v0;
        *(float4*)&C[base + 4] = v1;
    }
}

// ---------------- RoPE (in-place) — UNCHANGED from passing round 7 ----------------
__global__ void rope_naive(float* __restrict__ X, const int* __restrict__ pos_ids, int nh) {
    int idx = blockIdx.x * 256 + threadIdx.x;   // over S * nh * 64
    int total = 2048 * nh * 64;
    if (idx >= total) return;
    int i = idx % 64;
    int h = (idx / 64) % nh;
    int s = idx / (64 * nh);
    const float LN10000 = 9.210340371976184f;
    float inv = __expf(-((float)(2 * i) / 128.0f) * LN10000);
    float ang = (float)pos_ids[s] * inv;
    float c = cosf(ang);
    float sn = sinf(ang);
    float* row = X + (size_t)s * (nh * 128) + h * 128;
    float x1 = row[i];
    float x2 = row[i + 64];
    row[i]      = x1 * c - x2 * sn;
    row[i + 64] = x2 * c + x1 * sn;
}

// ---------------- naive attention — UNCHANGED from passing round 7 ----------------
__global__ __launch_bounds__(128) void attn_naive(const float* __restrict__ Q,
                                                  const float* __restrict__ K,
                                                  const float* __restrict__ V,
                                                  float* __restrict__ O) {
    __shared__ float sc[2048];
    __shared__ float red[128];

    const int q  = blockIdx.x;   // 0..2047
    const int h  = blockIdx.y;   // 0..31
    const int kh = h >> 2;       // GQA: 4 query heads per kv head
    const int t  = threadIdx.x;  // 0..127

    const float scale = 0.08838834764831845f;   // 1/sqrt(128)
    const float* qrow = Q + (size_t)q * 4096 + h * 128;

    float mx = -INFINITY;
    for (int k = t; k <= q; k += 128) {
        const float* krow = K + (size_t)k * 1024 + kh * 128;
        float s = 0.f;
        for (int d = 0; d < 128; d++) s += qrow[d] * krow[d];
        s *= scale;
        sc[k] = s;
        mx = fmaxf(mx, s);
    }
    red[t] = mx;
    __syncthreads();
    for (int off = 64; off > 0; off >>= 1) {
        if (t < off) red[t] = fmaxf(red[t], red[t + off]);
        __syncthreads();
    }
    float m = red[0];
    __syncthreads();

    float sum = 0.f;
    for (int k = t; k <= q; k += 128) {
        float p = __expf(sc[k] - m);
        sc[k] = p;
        sum += p;
    }
    red[t] = sum;
    __syncthreads();
    for (int off = 64; off > 0; off >>= 1) {
        if (t < off) red[t] += red[t + off];
        __syncthreads();
    }
    float invl = 1.f / red[0];

    float acc = 0.f;
    for (int k = 0; k <= q; k++) {
        acc += sc[k] * V[(size_t)k * 1024 + kh * 128 + t];
    }
    O[(size_t)q * 4096 + h * 128 + t] = acc * invl;
}

// ---------------- launch ----------------
extern "C" void kernel_launch(void* const* d_in, const int* in_sizes, int n_in,
                              void* d_out, int out_size) {
    // Size-driven input identification (identical to passing round 7).
    int i16[2] = {-1, -1}, n16 = 0;
    int i4[2]  = {-1, -1}, n4  = 0;
    int iHS = -1, iPOS = -1;
    for (int i = 0; i < 6; i++) {
        int s = in_sizes[i];
        if (s == 16777216)      { if (n16 < 2) i16[n16++] = i; }
        else if (s == 4194304)  { if (n4  < 2) i4[n4++]   = i; }
        else if (s == 8388608)  iHS = i;
        else                    iPOS = i;   // 2048
    }
    int iWq, iWo;
    if (i16[1] == i16[0] + 1) { iWo = i16[0]; iWq = i16[1]; }   // name-sorted: Wo,Wq adjacent
    else                      { iWq = i16[0]; iWo = i16[1]; }   // dict order: Wq ... Wo
    const int iWk = i4[0];
    const int iWv = i4[1];

    const float* hs  = (const float*)d_in[iHS];
    const int*   pos = (const int*)d_in[iPOS];
    const float* Wq  = (const float*)d_in[iWq];
    const float* Wk  = (const float*)d_in[iWk];
    const float* Wv  = (const float*)d_in[iWv];
    const float* Wo  = (const float*)d_in[iWo];
    float* out = (float*)d_out;

    float *Q, *K, *V, *A;
    cudaGetSymbolAddress((void**)&Q, g_Q);
    cudaGetSymbolAddress((void**)&K, g_K);
    cudaGetSymbolAddress((void**)&V, g_V);
    cudaGetSymbolAddress((void**)&A, g_A);

    // QKV projections (tiled SGEMM)
    {
        dim3 gq(4096 / BN, 2048 / BM);
        sgemm_kernel<<<gq, 256>>>(hs, Wq, Q, 2048, 4096, 4096);
        dim3 gkv(1024 / BN, 2048 / BM);
        sgemm_kernel<<<gkv, 256>>>(hs, Wk, K, 2048, 1024, 4096);
        sgemm_kernel<<<gkv, 256>>>(hs, Wv, V, 2048, 1024, 4096);
    }

    // RoPE on Q (32 heads) and K (8 heads)
    {
        int totq = 2048 * 32 * 64;
        rope_naive<<<(totq + 255) / 256, 256>>>(Q, pos, 32);
        int totk = 2048 * 8 * 64;
        rope_naive<<<(totk + 255) / 256, 256>>>(K, pos, 8);
    }

    // Attention (naive, proven correct)
    {
        dim3 ga(2048, 32);
        attn_naive<<<ga, 128>>>(Q, K, V, A);
    }

    // Output projection (tiled SGEMM)
    {
        dim3 go(4096 / BN, 2048 / BM);
        sgemm_kernel<<<go, 256>>>(A, Wo, out, 2048, 4096, 4096);
    }
}

// round 10
// speedup vs baseline: 4.7433x; 3.2015x over previous
#include <cuda_runtime.h>
#include <math.h>

// ---------------- scratch (no allocations allowed) ----------------
__device__ float g_Q[2048 * 4096];   // [S, NH*D]
__device__ float g_K[2048 * 1024];   // [S, NKV*D]
__device__ float g_V[2048 * 1024];   // [S, NKV*D]
__device__ float g_A[2048 * 4096];   // attention output [S, NH*D]

// ---------------- tiled SGEMM: C[M,N] = A[M,K] @ B[K,N], row-major ----------------
#define BM 128
#define BN 128
#define BKK 16

__global__ __launch_bounds__(256) void sgemm_kernel(const float* __restrict__ A,
                                                    const float* __restrict__ B,
                                                    float* __restrict__ C,
                                                    int M, int N, int K) {
    __shared__ float As[BKK][BM + 4];
    __shared__ float Bs[BKK][BN + 4];

    const int bm = blockIdx.y * BM;
    const int bn = blockIdx.x * BN;
    const int t = threadIdx.x;
    const int tm0 = (t >> 4) * 8;
    const int tn0 = (t & 15) * 8;

    float acc[8][8];
#pragma unroll
    for (int i = 0; i < 8; i++)
#pragma unroll
        for (int j = 0; j < 8; j++) acc[i][j] = 0.f;

    const float* Ab = A + (size_t)bm * K;
    const float* Bb = B + bn;

    for (int k0 = 0; k0 < K; k0 += BKK) {
#pragma unroll
        for (int i = 0; i < 2; i++) {
            int idx = t + i * 256;
            int row = idx >> 2;
            int c4  = idx & 3;
            float4 v = *(const float4*)(Ab + (size_t)row * K + k0 + c4 * 4);
            As[c4 * 4 + 0][row] = v.x;
            As[c4 * 4 + 1][row] = v.y;
            As[c4 * 4 + 2][row] = v.z;
            As[c4 * 4 + 3][row] = v.w;
        }
#pragma unroll
        for (int i = 0; i < 2; i++) {
            int idx = t + i * 256;
            int row = idx >> 5;
            int c4  = idx & 31;
            *(float4*)&Bs[row][c4 * 4] =
                *(const float4*)(Bb + (size_t)(k0 + row) * N + c4 * 4);
        }
        __syncthreads();

#pragma unroll
        for (int k = 0; k < BKK; k++) {
            float a[8], b[8];
#pragma unroll
            for (int x = 0; x < 8; x++) a[x] = As[k][tm0 + x];
#pragma unroll
            for (int x = 0; x < 8; x++) b[x] = Bs[k][tn0 + x];
#pragma unroll
            for (int i = 0; i < 8; i++)
#pragma unroll
                for (int j = 0; j < 8; j++) acc[i][j] += a[i] * b[j];
        }
        __syncthreads();
    }

#pragma unroll
    for (int i = 0; i < 8; i++) {
        float4 v0 = make_float4(acc[i][0], acc[i][1], acc[i][2], acc[i][3]);
        float4 v1 = make_float4(acc[i][4], acc[i][5], acc[i][6], acc[i][7]);
        size_t base = (size_t)(bm + tm0 + i) * N + bn + tn0;
        *(float4*)&C[base]     = v0;
        *(float4*)&C[base + 4] = v1;
    }
}

// ---------------- RoPE (in-place) — UNCHANGED (proven) ----------------
__global__ void rope_naive(float* __restrict__ X, const int* __restrict__ pos_ids, int nh) {
    int idx = blockIdx.x * 256 + threadIdx.x;
    int total = 2048 * nh * 64;
    if (idx >= total) return;
    int i = idx % 64;
    int h = (idx / 64) % nh;
    int s = idx / (64 * nh);
    const float LN10000 = 9.210340371976184f;
    float inv = __expf(-((float)(2 * i) / 128.0f) * LN10000);
    float ang = (float)pos_ids[s] * inv;
    float c = cosf(ang);
    float sn = sinf(ang);
    float* row = X + (size_t)s * (nh * 128) + h * 128;
    float x1 = row[i];
    float x2 = row[i + 64];
    row[i]      = x1 * c - x2 * sn;
    row[i + 64] = x2 * c + x1 * sn;
}

// ---------------- attention v2.1: 4 query rows per block (Q-loader FIXED) ----------------
// Two-pass softmax, K/V reads amortized over 4 query rows.
// Static smem 35.8KB (< 48KB: no cudaFuncSetAttribute).
// Grid: (512 q-blocks, 32 heads), 256 threads.
__global__ __launch_bounds__(256) void attn_q4(const float* __restrict__ Q,
                                               const float* __restrict__ K,
                                               const float* __restrict__ V,
                                               float* __restrict__ O) {
    __shared__ float sc[4][2048];   // scores/probs per row
    __shared__ float qs[4][128];    // the 4 Q rows
    __shared__ float red[256];      // reductions

    const int qb = blockIdx.x;      // 0..511
    const int h  = blockIdx.y;      // 0..31
    const int kh = h >> 2;          // GQA: 4 q-heads per kv head
    const int t  = threadIdx.x;     // 0..255
    const int q0 = qb * 4;
    const int qmax = q0 + 3;        // last (longest) causal row in this block

    const float scale = 0.08838834764831845f;   // 1/sqrt(128)

    // load the 4 Q rows into smem — FIX: strided loop covers all 512 elements
    for (int i = t; i < 512; i += 256) {
        int r = i >> 7;             // 0..3
        int d = i & 127;
        qs[r][d] = Q[(size_t)(q0 + r) * 4096 + h * 128 + d];
    }
    __syncthreads();

    // ---- score phase: 256 threads = 64 key-slots x 4 rows ----
    const int r  = t & 3;           // row this thread scores
    const int ks = t >> 2;          // key slot 0..63
    float mx = -INFINITY;
    for (int k = ks; k <= qmax; k += 64) {
        const float* krow = K + (size_t)k * 1024 + kh * 128;
        float s = 0.f;
#pragma unroll 8
        for (int d4 = 0; d4 < 128; d4 += 4) {
            float4 kv = *(const float4*)(krow + d4);
            float4 qv = *(const float4*)&qs[r][d4];
            s += qv.x * kv.x + qv.y * kv.y + qv.z * kv.z + qv.w * kv.w;
        }
        s *= scale;
        if (k > q0 + r) s = -1e30f;     // per-row causal mask
        sc[r][k] = s;
        mx = fmaxf(mx, s);
    }

    // per-row max: reduce among threads with equal (t & 3) — strides 128..4
    red[t] = mx;
    __syncthreads();
    for (int off = 128; off >= 4; off >>= 1) {
        if (t < off) red[t] = fmaxf(red[t], red[t + off]);
        __syncthreads();
    }
    float mrow = red[r];            // row max
    __syncthreads();                // before red is reused

    // exp + per-row sum
    float sum = 0.f;
    for (int k = ks; k <= qmax; k += 64) {
        float p = __expf(sc[r][k] - mrow);   // masked entries -> 0
        sc[r][k] = p;
        sum += p;
    }
    red[t] = sum;
    __syncthreads();
    for (int off = 128; off >= 4; off >>= 1) {
        if (t < off) red[t] += red[t + off];
        __syncthreads();
    }
    // red[0..3] now hold row sums; keep them (no further writes to red)

    // ---- PV phase: 256 threads = 2 row-groups x 128 dims ----
    const int d   = t & 127;
    const int rp0 = (t >> 7) * 2;   // rows rp0, rp0+1
    const int rp1 = rp0 + 1;
    const float* vcol = V + (size_t)kh * 128 + d;

    float acc0 = 0.f, acc1 = 0.f;
    for (int k = 0; k <= qmax; k++) {       // masked probs are 0 -> safe for all rows
        float v = vcol[(size_t)k * 1024];
        acc0 += sc[rp0][k] * v;
        acc1 += sc[rp1][k] * v;
    }

    float inv0 = 1.f / red[rp0];
    float inv1 = 1.f / red[rp1];
    O[(size_t)(q0 + rp0) * 4096 + h * 128 + d] = acc0 * inv0;
    O[(size_t)(q0 + rp1) * 4096 + h * 128 + d] = acc1 * inv1;
}

// ---------------- launch ----------------
extern "C" void kernel_launch(void* const* d_in, const int* in_sizes, int n_in,
                              void* d_out, int out_size) {
    // Size-driven input identification (identical to passing rounds 7/8).
    int i16[2] = {-1, -1}, n16 = 0;
    int i4[2]  = {-1, -1}, n4  = 0;
    int iHS = -1, iPOS = -1;
    for (int i = 0; i < 6; i++) {
        int s = in_sizes[i];
        if (s == 16777216)      { if (n16 < 2) i16[n16++] = i; }
        else if (s == 4194304)  { if (n4  < 2) i4[n4++]   = i; }
        else if (s == 8388608)  iHS = i;
        else                    iPOS = i;   // 2048
    }
    int iWq, iWo;
    if (i16[1] == i16[0] + 1) { iWo = i16[0]; iWq = i16[1]; }   // name-sorted: Wo,Wq adjacent
    else                      { iWq = i16[0]; iWo = i16[1]; }   // dict order: Wq ... Wo
    const int iWk = i4[0];
    const int iWv = i4[1];

    const float* hs  = (const float*)d_in[iHS];
    const int*   pos = (const int*)d_in[iPOS];
    const float* Wq  = (const float*)d_in[iWq];
    const float* Wk  = (const float*)d_in[iWk];
    const float* Wv  = (const float*)d_in[iWv];
    const float* Wo  = (const float*)d_in[iWo];
    float* out = (float*)d_out;

    float *Q, *K, *V, *A;
    cudaGetSymbolAddress((void**)&Q, g_Q);
    cudaGetSymbolAddress((void**)&K, g_K);
    cudaGetSymbolAddress((void**)&V, g_V);
    cudaGetSymbolAddress((void**)&A, g_A);

    // QKV projections (tiled SGEMM)
    {
        dim3 gq(4096 / BN, 2048 / BM);
        sgemm_kernel<<<gq, 256>>>(hs, Wq, Q, 2048, 4096, 4096);
        dim3 gkv(1024 / BN, 2048 / BM);
        sgemm_kernel<<<gkv, 256>>>(hs, Wk, K, 2048, 1024, 4096);
        sgemm_kernel<<<gkv, 256>>>(hs, Wv, V, 2048, 1024, 4096);
    }

    // RoPE on Q (32 heads) and K (8 heads)
    {
        int totq = 2048 * 32 * 64;
        rope_naive<<<(totq + 255) / 256, 256>>>(Q, pos, 32);
        int totk = 2048 * 8 * 64;
        rope_naive<<<(totk + 255) / 256, 256>>>(K, pos, 8);
    }

    // Attention (4 q-rows per block, fixed loader)
    {
        dim3 ga(512, 32);
        attn_q4<<<ga, 256>>>(Q, K, V, A);
    }

    // Output projection (tiled SGEMM)
    {
        dim3 go(4096 / BN, 2048 / BM);
        sgemm_kernel<<<go, 256>>>(A, Wo, out, 2048, 4096, 4096);
    }
}

// round 11
// speedup vs baseline: 5.8679x; 1.2371x over previous
#include <cuda_runtime.h>
#include <cuda_bf16.h>
#include <math.h>
#include <stdint.h>

// ---------------- scratch (no allocations allowed) ----------------
__device__ float g_Q[2048 * 4096];   // [S, NH*D]
__device__ float g_K[2048 * 1024];   // [S, NKV*D]
__device__ float g_V[2048 * 1024];   // [S, NKV*D]
__device__ float g_A[2048 * 4096];   // attention output [S, NH*D]

// ---------------- PTX helpers ----------------
__device__ __forceinline__ uint32_t smem_addr(const void* p) {
    return (uint32_t)__cvta_generic_to_shared(p);
}
__device__ __forceinline__ void ldsm_x4(uint32_t* r, uint32_t addr) {
    asm volatile("ldmatrix.sync.aligned.m8n8.x4.shared.b16 {%0,%1,%2,%3}, [%4];\n"
                 : "=r"(r[0]), "=r"(r[1]), "=r"(r[2]), "=r"(r[3]) : "r"(addr));
}
__device__ __forceinline__ void ldsm_x2_t(uint32_t* r, uint32_t addr) {
    asm volatile("ldmatrix.sync.aligned.m8n8.x2.trans.shared.b16 {%0,%1}, [%2];\n"
                 : "=r"(r[0]), "=r"(r[1]) : "r"(addr));
}
__device__ __forceinline__ void mma_bf16(float* d, const uint32_t* a, const uint32_t* b) {
    asm volatile("mma.sync.aligned.m16n8k16.row.col.f32.bf16.bf16.f32 "
                 "{%0,%1,%2,%3}, {%4,%5,%6,%7}, {%8,%9}, {%0,%1,%2,%3};\n"
                 : "+f"(d[0]), "+f"(d[1]), "+f"(d[2]), "+f"(d[3])
                 : "r"(a[0]), "r"(a[1]), "r"(a[2]), "r"(a[3]), "r"(b[0]), "r"(b[1]));
}

// ---------------- tensor-core GEMM (split-bf16, 3-term): C = A @ B ----------------
// A[M,K], B[K,N], C[M,N] all row-major fp32. Tiles 128x128x32; 8 warps (2x4),
// each warp computes 64x32 via 4x4 m16n8k16 mma tiles. fp32 values split into
// hi/lo bf16 at tile-load; acc += Ah*Bh + Ah*Bl + Al*Bh (fp32 accum).
// Static smem ~37.9KB. Pitches: A 40 bf16 (bank stride 20), B 136 (stride 4) —
// conflict-free ldmatrix phases.
__global__ __launch_bounds__(256) void mma_gemm(const float* __restrict__ A,
                                                const float* __restrict__ B,
                                                float* __restrict__ C,
                                                int M, int N, int K) {
    __shared__ __nv_bfloat16 sAh[128][40];
    __shared__ __nv_bfloat16 sAl[128][40];
    __shared__ __nv_bfloat16 sBh[32][136];
    __shared__ __nv_bfloat16 sBl[32][136];

    const int t    = threadIdx.x;
    const int lane = t & 31;
    const int wid  = t >> 5;
    const int warp_m = wid & 1;    // 0..1 -> 64-row half
    const int warp_n = wid >> 1;   // 0..3 -> 32-col quarter
    const int bm = blockIdx.y * 128;
    const int bn = blockIdx.x * 128;

    float acc[4][4][4];
#pragma unroll
    for (int mi = 0; mi < 4; mi++)
#pragma unroll
        for (int ni = 0; ni < 4; ni++)
#pragma unroll
            for (int r = 0; r < 4; r++) acc[mi][ni][r] = 0.f;

    for (int k0 = 0; k0 < K; k0 += 32) {
        // ---- load + split A tile: 128 rows x 32 k ----
#pragma unroll
        for (int i = 0; i < 4; i++) {
            int id  = t + i * 256;        // 0..1023 float4s
            int row = id >> 3;            // 0..127
            int c4  = id & 7;             // 0..7  (k offset c4*4)
            float4 v = *(const float4*)(A + (size_t)(bm + row) * K + k0 + c4 * 4);
            float vv[4] = {v.x, v.y, v.z, v.w};
#pragma unroll
            for (int j = 0; j < 4; j++) {
                __nv_bfloat16 hi = __float2bfloat16(vv[j]);
                __nv_bfloat16 lo = __float2bfloat16(vv[j] - __bfloat162float(hi));
                sAh[row][c4 * 4 + j] = hi;
                sAl[row][c4 * 4 + j] = lo;
            }
        }
        // ---- load + split B tile: 32 k x 128 n ----
#pragma unroll
        for (int i = 0; i < 4; i++) {
            int id  = t + i * 256;
            int row = id >> 5;            // 0..31
            int c4  = id & 31;            // 0..31 (n offset c4*4)
            float4 v = *(const float4*)(B + (size_t)(k0 + row) * N + bn + c4 * 4);
            float vv[4] = {v.x, v.y, v.z, v.w};
#pragma unroll
            for (int j = 0; j < 4; j++) {
                __nv_bfloat16 hi = __float2bfloat16(vv[j]);
                __nv_bfloat16 lo = __float2bfloat16(vv[j] - __bfloat162float(hi));
                sBh[row][c4 * 4 + j] = hi;
                sBl[row][c4 * 4 + j] = lo;
            }
        }
        __syncthreads();

#pragma unroll
        for (int kk = 0; kk < 32; kk += 16) {
            // A fragments: rows warp_m*64 + mi*16 + (lane&15), col kk + (lane>>4)*8
            uint32_t ah[4][4], al[4][4];
#pragma unroll
            for (int mi = 0; mi < 4; mi++) {
                int row = warp_m * 64 + mi * 16 + (lane & 15);
                int col = kk + ((lane >> 4) << 3);
                ldsm_x4(ah[mi], smem_addr(&sAh[row][col]));
                ldsm_x4(al[mi], smem_addr(&sAl[row][col]));
            }
            // B fragments: rows kk + (lane&15), col warp_n*32 + ni*8 (trans)
            uint32_t bh[4][2], bl[4][2];
#pragma unroll
            for (int ni = 0; ni < 4; ni++) {
                int row = kk + (lane & 15);
                int col = warp_n * 32 + ni * 8;
                ldsm_x2_t(bh[ni], smem_addr(&sBh[row][col]));
                ldsm_x2_t(bl[ni], smem_addr(&sBl[row][col]));
            }
#pragma unroll
            for (int mi = 0; mi < 4; mi++)
#pragma unroll
                for (int ni = 0; ni < 4; ni++) {
                    mma_bf16(acc[mi][ni], ah[mi], bh[ni]);
                    mma_bf16(acc[mi][ni], ah[mi], bl[ni]);
                    mma_bf16(acc[mi][ni], al[mi], bh[ni]);
                }
        }
        __syncthreads();
    }

    // ---- epilogue: fragment layout c0,c1 = (row gid, col tid*2..+1); c2,c3 = row gid+8
    const int gid = lane >> 2;
    const int tid = lane & 3;
#pragma unroll
    for (int mi = 0; mi < 4; mi++)
#pragma unroll
        for (int ni = 0; ni < 4; ni++) {
            int row = bm + warp_m * 64 + mi * 16 + gid;
            int col = bn + warp_n * 32 + ni * 8 + tid * 2;
            C[(size_t)row * N + col]           = acc[mi][ni][0];
            C[(size_t)row * N + col + 1]       = acc[mi][ni][1];
            C[(size_t)(row + 8) * N + col]     = acc[mi][ni][2];
            C[(size_t)(row + 8) * N + col + 1] = acc[mi][ni][3];
        }
}

// ---------------- RoPE (in-place) — UNCHANGED (proven) ----------------
__global__ void rope_naive(float* __restrict__ X, const int* __restrict__ pos_ids, int nh) {
    int idx = blockIdx.x * 256 + threadIdx.x;
    int total = 2048 * nh * 64;
    if (idx >= total) return;
    int i = idx % 64;
    int h = (idx / 64) % nh;
    int s = idx / (64 * nh);
    const float LN10000 = 9.210340371976184f;
    float inv = __expf(-((float)(2 * i) / 128.0f) * LN10000);
    float ang = (float)pos_ids[s] * inv;
    float c = cosf(ang);
    float sn = sinf(ang);
    float* row = X + (size_t)s * (nh * 128) + h * 128;
    float x1 = row[i];
    float x2 = row[i + 64];
    row[i]      = x1 * c - x2 * sn;
    row[i + 64] = x2 * c + x1 * sn;
}

// ---------------- attention: 4 query rows per block — UNCHANGED (proven) ----------------
__global__ __launch_bounds__(256) void attn_q4(const float* __restrict__ Q,
                                               const float* __restrict__ K,
                                               const float* __restrict__ V,
                                               float* __restrict__ O) {
    __shared__ float sc[4][2048];
    __shared__ float qs[4][128];
    __shared__ float red[256];

    const int qb = blockIdx.x;
    const int h  = blockIdx.y;
    const int kh = h >> 2;
    const int t  = threadIdx.x;
    const int q0 = qb * 4;
    const int qmax = q0 + 3;

    const float scale = 0.08838834764831845f;

    for (int i = t; i < 512; i += 256) {
        int r = i >> 7;
        int d = i & 127;
        qs[r][d] = Q[(size_t)(q0 + r) * 4096 + h * 128 + d];
    }
    __syncthreads();

    const int r  = t & 3;
    const int ks = t >> 2;
    float mx = -INFINITY;
    for (int k = ks; k <= qmax; k += 64) {
        const float* krow = K + (size_t)k * 1024 + kh * 128;
        float s = 0.f;
#pragma unroll 8
        for (int d4 = 0; d4 < 128; d4 += 4) {
            float4 kv = *(const float4*)(krow + d4);
            float4 qv = *(const float4*)&qs[r][d4];
            s += qv.x * kv.x + qv.y * kv.y + qv.z * kv.z + qv.w * kv.w;
        }
        s *= scale;
        if (k > q0 + r) s = -1e30f;
        sc[r][k] = s;
        mx = fmaxf(mx, s);
    }

    red[t] = mx;
    __syncthreads();
    for (int off = 128; off >= 4; off >>= 1) {
        if (t < off) red[t] = fmaxf(red[t], red[t + off]);
        __syncthreads();
    }
    float mrow = red[r];
    __syncthreads();

    float sum = 0.f;
    for (int k = ks; k <= qmax; k += 64) {
        float p = __expf(sc[r][k] - mrow);
        sc[r][k] = p;
        sum += p;
    }
    red[t] = sum;
    __syncthreads();
    for (int off = 128; off >= 4; off >>= 1) {
        if (t < off) red[t] += red[t + off];
        __syncthreads();
    }

    const int d   = t & 127;
    const int rp0 = (t >> 7) * 2;
    const int rp1 = rp0 + 1;
    const float* vcol = V + (size_t)kh * 128 + d;

    float acc0 = 0.f, acc1 = 0.f;
    for (int k = 0; k <= qmax; k++) {
        float v = vcol[(size_t)k * 1024];
        acc0 += sc[rp0][k] * v;
        acc1 += sc[rp1][k] * v;
    }

    float inv0 = 1.f / red[rp0];
    float inv1 = 1.f / red[rp1];
    O[(size_t)(q0 + rp0) * 4096 + h * 128 + d] = acc0 * inv0;
    O[(size_t)(q0 + rp1) * 4096 + h * 128 + d] = acc1 * inv1;
}

// ---------------- launch ----------------
extern "C" void kernel_launch(void* const* d_in, const int* in_sizes, int n_in,
                              void* d_out, int out_size) {
    // Size-driven input identification (identical to passing rounds).
    int i16[2] = {-1, -1}, n16 = 0;
    int i4[2]  = {-1, -1}, n4  = 0;
    int iHS = -1, iPOS = -1;
    for (int i = 0; i < 6; i++) {
        int s = in_sizes[i];
        if (s == 16777216)      { if (n16 < 2) i16[n16++] = i; }
        else if (s == 4194304)  { if (n4  < 2) i4[n4++]   = i; }
        else if (s == 8388608)  iHS = i;
        else                    iPOS = i;   // 2048
    }
    int iWq, iWo;
    if (i16[1] == i16[0] + 1) { iWo = i16[0]; iWq = i16[1]; }   // name-sorted: Wo,Wq adjacent
    else                      { iWq = i16[0]; iWo = i16[1]; }   // dict order: Wq ... Wo
    const int iWk = i4[0];
    const int iWv = i4[1];

    const float* hs  = (const float*)d_in[iHS];
    const int*   pos = (const int*)d_in[iPOS];
    const float* Wq  = (const float*)d_in[iWq];
    const float* Wk  = (const float*)d_in[iWk];
    const float* Wv  = (const float*)d_in[iWv];
    const float* Wo  = (const float*)d_in[iWo];
    float* out = (float*)d_out;

    float *Q, *K, *V, *A;
    cudaGetSymbolAddress((void**)&Q, g_Q);
    cudaGetSymbolAddress((void**)&K, g_K);
    cudaGetSymbolAddress((void**)&V, g_V);
    cudaGetSymbolAddress((void**)&A, g_A);

    // QKV projections (tensor-core split-bf16 GEMM)
    {
        dim3 gq(4096 / 128, 2048 / 128);
        mma_gemm<<<gq, 256>>>(hs, Wq, Q, 2048, 4096, 4096);
        dim3 gkv(1024 / 128, 2048 / 128);
        mma_gemm<<<gkv, 256>>>(hs, Wk, K, 2048, 1024, 4096);
        mma_gemm<<<gkv, 256>>>(hs, Wv, V, 2048, 1024, 4096);
    }

    // RoPE on Q (32 heads) and K (8 heads)
    {
        int totq = 2048 * 32 * 64;
        rope_naive<<<(totq + 255) / 256, 256>>>(Q, pos, 32);
        int totk = 2048 * 8 * 64;
        rope_naive<<<(totk + 255) / 256, 256>>>(K, pos, 8);
    }

    // Attention (4 q-rows per block)
    {
        dim3 ga(512, 32);
        attn_q4<<<ga, 256>>>(Q, K, V, A);
    }

    // Output projection (tensor-core split-bf16 GEMM)
    {
        dim3 go(4096 / 128, 2048 / 128);
        mma_gemm<<<go, 256>>>(A, Wo, out, 2048, 4096, 4096);
    }
}

// round 12
// speedup vs baseline: 6.2474x; 1.0647x over previous
#include <cuda_runtime.h>
#include <cuda_bf16.h>
#include <math.h>
#include <stdint.h>

// ---------------- scratch (no allocations allowed) ----------------
__device__ float g_Q[2048 * 4096];   // [S, NH*D]
__device__ float g_K[2048 * 1024];   // [S, NKV*D]
__device__ float g_V[2048 * 1024];   // [S, NKV*D]
__device__ float g_A[2048 * 4096];   // attention output [S, NH*D]

// pre-split bf16 hi/lo operands
__device__ __nv_bfloat16 g_hsh[2048 * 4096], g_hsl[2048 * 4096];
__device__ __nv_bfloat16 g_Wqh[4096 * 4096], g_Wql[4096 * 4096];
__device__ __nv_bfloat16 g_Wkh[4096 * 1024], g_Wkl[4096 * 1024];
__device__ __nv_bfloat16 g_Wvh[4096 * 1024], g_Wvl[4096 * 1024];
__device__ __nv_bfloat16 g_Woh[4096 * 4096], g_Wol[4096 * 4096];
__device__ __nv_bfloat16 g_Ahh[2048 * 4096], g_Ahl[2048 * 4096];

// ---------------- PTX helpers ----------------
__device__ __forceinline__ uint32_t smem_addr(const void* p) {
    return (uint32_t)__cvta_generic_to_shared(p);
}
__device__ __forceinline__ void ldsm_x4(uint32_t* r, uint32_t addr) {
    asm volatile("ldmatrix.sync.aligned.m8n8.x4.shared.b16 {%0,%1,%2,%3}, [%4];\n"
                 : "=r"(r[0]), "=r"(r[1]), "=r"(r[2]), "=r"(r[3]) : "r"(addr));
}
__device__ __forceinline__ void ldsm_x2_t(uint32_t* r, uint32_t addr) {
    asm volatile("ldmatrix.sync.aligned.m8n8.x2.trans.shared.b16 {%0,%1}, [%2];\n"
                 : "=r"(r[0]), "=r"(r[1]) : "r"(addr));
}
__device__ __forceinline__ void mma_bf16(float* d, const uint32_t* a, const uint32_t* b) {
    asm volatile("mma.sync.aligned.m16n8k16.row.col.f32.bf16.bf16.f32 "
                 "{%0,%1,%2,%3}, {%4,%5,%6,%7}, {%8,%9}, {%0,%1,%2,%3};\n"
                 : "+f"(d[0]), "+f"(d[1]), "+f"(d[2]), "+f"(d[3])
                 : "r"(a[0]), "r"(a[1]), "r"(a[2]), "r"(a[3]), "r"(b[0]), "r"(b[1]));
}

// ---------------- fp32 -> (hi, lo) bf16 split, vectorized ----------------
__global__ void split_fp32(const float* __restrict__ X,
                           __nv_bfloat16* __restrict__ H,
                           __nv_bfloat16* __restrict__ L, int n4) {
    int i = blockIdx.x * 256 + threadIdx.x;
    if (i >= n4) return;
    float4 v = ((const float4*)X)[i];
    float vv[4] = {v.x, v.y, v.z, v.w};
    __nv_bfloat16 h[4], l[4];
#pragma unroll
    for (int j = 0; j < 4; j++) {
        h[j] = __float2bfloat16(vv[j]);
        l[j] = __float2bfloat16(vv[j] - __bfloat162float(h[j]));
    }
    ((uint2*)H)[i] = *(uint2*)h;
    ((uint2*)L)[i] = *(uint2*)l;
}

// ---------------- tensor-core GEMM (pre-split bf16, 3-term): C = A @ B ----------------
// A hi/lo [M,K], B hi/lo [K,N] bf16 row-major; C [M,N] fp32.
// Tiles 128x128x32; 8 warps (2x4), each 64x32 via 4x4 m16n8k16 mma.
// acc += Ah*Bh + Ah*Bl + Al*Bh. Static smem ~37.9KB, vectorized STS.64 loads.
__global__ __launch_bounds__(256) void mma_gemm_bf(const __nv_bfloat16* __restrict__ Ah,
                                                   const __nv_bfloat16* __restrict__ Al,
                                                   const __nv_bfloat16* __restrict__ Bh,
                                                   const __nv_bfloat16* __restrict__ Bl,
                                                   float* __restrict__ C,
                                                   int M, int N, int K) {
    __shared__ __align__(16) __nv_bfloat16 sAh[128][40];
    __shared__ __align__(16) __nv_bfloat16 sAl[128][40];
    __shared__ __align__(16) __nv_bfloat16 sBh[32][136];
    __shared__ __align__(16) __nv_bfloat16 sBl[32][136];

    const int t    = threadIdx.x;
    const int lane = t & 31;
    const int wid  = t >> 5;
    const int warp_m = wid & 1;
    const int warp_n = wid >> 1;
    const int bm = blockIdx.y * 128;
    const int bn = blockIdx.x * 128;

    float acc[4][4][4];
#pragma unroll
    for (int mi = 0; mi < 4; mi++)
#pragma unroll
        for (int ni = 0; ni < 4; ni++)
#pragma unroll
            for (int r = 0; r < 4; r++) acc[mi][ni][r] = 0.f;

    for (int k0 = 0; k0 < K; k0 += 32) {
        // ---- A tile: 128 rows x 32 k, 8-element granules ----
#pragma unroll
        for (int i = 0; i < 2; i++) {
            int id  = t + i * 256;        // 0..511 granules
            int row = id >> 2;            // 0..127
            int g   = id & 3;             // 0..3
            size_t src = (size_t)(bm + row) * K + k0 + g * 8;
            uint4 vh = *(const uint4*)(Ah + src);
            uint4 vl = *(const uint4*)(Al + src);
            *(uint2*)&sAh[row][g * 8]     = make_uint2(vh.x, vh.y);
            *(uint2*)&sAh[row][g * 8 + 4] = make_uint2(vh.z, vh.w);
            *(uint2*)&sAl[row][g * 8]     = make_uint2(vl.x, vl.y);
            *(uint2*)&sAl[row][g * 8 + 4] = make_uint2(vl.z, vl.w);
        }
        // ---- B tile: 32 k x 128 n ----
#pragma unroll
        for (int i = 0; i < 2; i++) {
            int id  = t + i * 256;
            int row = id >> 4;            // 0..31
            int g   = id & 15;            // 0..15
            size_t src = (size_t)(k0 + row) * N + bn + g * 8;
            uint4 vh = *(const uint4*)(Bh + src);
            uint4 vl = *(const uint4*)(Bl + src);
            *(uint2*)&sBh[row][g * 8]     = make_uint2(vh.x, vh.y);
            *(uint2*)&sBh[row][g * 8 + 4] = make_uint2(vh.z, vh.w);
            *(uint2*)&sBl[row][g * 8]     = make_uint2(vl.x, vl.y);
            *(uint2*)&sBl[row][g * 8 + 4] = make_uint2(vl.z, vl.w);
        }
        __syncthreads();

#pragma unroll
        for (int kk = 0; kk < 32; kk += 16) {
            uint32_t ah[4][4], al[4][4];
#pragma unroll
            for (int mi = 0; mi < 4; mi++) {
                int row = warp_m * 64 + mi * 16 + (lane & 15);
                int col = kk + ((lane >> 4) << 3);
                ldsm_x4(ah[mi], smem_addr(&sAh[row][col]));
                ldsm_x4(al[mi], smem_addr(&sAl[row][col]));
            }
            uint32_t bh[4][2], bl[4][2];
#pragma unroll
            for (int ni = 0; ni < 4; ni++) {
                int row = kk + (lane & 15);
                int col = warp_n * 32 + ni * 8;
                ldsm_x2_t(bh[ni], smem_addr(&sBh[row][col]));
                ldsm_x2_t(bl[ni], smem_addr(&sBl[row][col]));
            }
#pragma unroll
            for (int mi = 0; mi < 4; mi++)
#pragma unroll
                for (int ni = 0; ni < 4; ni++) {
                    mma_bf16(acc[mi][ni], ah[mi], bh[ni]);
                    mma_bf16(acc[mi][ni], ah[mi], bl[ni]);
                    mma_bf16(acc[mi][ni], al[mi], bh[ni]);
                }
        }
        __syncthreads();
    }

    const int gid = lane >> 2;
    const int tid = lane & 3;
#pragma unroll
    for (int mi = 0; mi < 4; mi++)
#pragma unroll
        for (int ni = 0; ni < 4; ni++) {
            int row = bm + warp_m * 64 + mi * 16 + gid;
            int col = bn + warp_n * 32 + ni * 8 + tid * 2;
            C[(size_t)row * N + col]           = acc[mi][ni][0];
            C[(size_t)row * N + col + 1]       = acc[mi][ni][1];
            C[(size_t)(row + 8) * N + col]     = acc[mi][ni][2];
            C[(size_t)(row + 8) * N + col + 1] = acc[mi][ni][3];
        }
}

// ---------------- RoPE (in-place) — UNCHANGED (proven) ----------------
__global__ void rope_naive(float* __restrict__ X, const int* __restrict__ pos_ids, int nh) {
    int idx = blockIdx.x * 256 + threadIdx.x;
    int total = 2048 * nh * 64;
    if (idx >= total) return;
    int i = idx % 64;
    int h = (idx / 64) % nh;
    int s = idx / (64 * nh);
    const float LN10000 = 9.210340371976184f;
    float inv = __expf(-((float)(2 * i) / 128.0f) * LN10000);
    float ang = (float)pos_ids[s] * inv;
    float c = cosf(ang);
    float sn = sinf(ang);
    float* row = X + (size_t)s * (nh * 128) + h * 128;
    float x1 = row[i];
    float x2 = row[i + 64];
    row[i]      = x1 * c - x2 * sn;
    row[i + 64] = x2 * c + x1 * sn;
}

// ---------------- attention: 4 query rows per block — UNCHANGED (proven) ----------------
__global__ __launch_bounds__(256) void attn_q4(const float* __restrict__ Q,
                                               const float* __restrict__ K,
                                               const float* __restrict__ V,
                                               float* __restrict__ O) {
    __shared__ float sc[4][2048];
    __shared__ float qs[4][128];
    __shared__ float red[256];

    const int qb = blockIdx.x;
    const int h  = blockIdx.y;
    const int kh = h >> 2;
    const int t  = threadIdx.x;
    const int q0 = qb * 4;
    const int qmax = q0 + 3;

    const float scale = 0.08838834764831845f;

    for (int i = t; i < 512; i += 256) {
        int r = i >> 7;
        int d = i & 127;
        qs[r][d] = Q[(size_t)(q0 + r) * 4096 + h * 128 + d];
    }
    __syncthreads();

    const int r  = t & 3;
    const int ks = t >> 2;
    float mx = -INFINITY;
    for (int k = ks; k <= qmax; k += 64) {
        const float* krow = K + (size_t)k * 1024 + kh * 128;
        float s = 0.f;
#pragma unroll 8
        for (int d4 = 0; d4 < 128; d4 += 4) {
            float4 kv = *(const float4*)(krow + d4);
            float4 qv = *(const float4*)&qs[r][d4];
            s += qv.x * kv.x + qv.y * kv.y + qv.z * kv.z + qv.w * kv.w;
        }
        s *= scale;
        if (k > q0 + r) s = -1e30f;
        sc[r][k] = s;
        mx = fmaxf(mx, s);
    }

    red[t] = mx;
    __syncthreads();
    for (int off = 128; off >= 4; off >>= 1) {
        if (t < off) red[t] = fmaxf(red[t], red[t + off]);
        __syncthreads();
    }
    float mrow = red[r];
    __syncthreads();

    float sum = 0.f;
    for (int k = ks; k <= qmax; k += 64) {
        float p = __expf(sc[r][k] - mrow);
        sc[r][k] = p;
        sum += p;
    }
    red[t] = sum;
    __syncthreads();
    for (int off = 128; off >= 4; off >>= 1) {
        if (t < off) red[t] += red[t + off];
        __syncthreads();
    }

    const int d   = t & 127;
    const int rp0 = (t >> 7) * 2;
    const int rp1 = rp0 + 1;
    const float* vcol = V + (size_t)kh * 128 + d;

    float acc0 = 0.f, acc1 = 0.f;
    for (int k = 0; k <= qmax; k++) {
        float v = vcol[(size_t)k * 1024];
        acc0 += sc[rp0][k] * v;
        acc1 += sc[rp1][k] * v;
    }

    float inv0 = 1.f / red[rp0];
    float inv1 = 1.f / red[rp1];
    O[(size_t)(q0 + rp0) * 4096 + h * 128 + d] = acc0 * inv0;
    O[(size_t)(q0 + rp1) * 4096 + h * 128 + d] = acc1 * inv1;
}

// ---------------- launch ----------------
extern "C" void kernel_launch(void* const* d_in, const int* in_sizes, int n_in,
                              void* d_out, int out_size) {
    // Size-driven input identification (identical to passing rounds).
    int i16[2] = {-1, -1}, n16 = 0;
    int i4[2]  = {-1, -1}, n4  = 0;
    int iHS = -1, iPOS = -1;
    for (int i = 0; i < 6; i++) {
        int s = in_sizes[i];
        if (s == 16777216)      { if (n16 < 2) i16[n16++] = i; }
        else if (s == 4194304)  { if (n4  < 2) i4[n4++]   = i; }
        else if (s == 8388608)  iHS = i;
        else                    iPOS = i;   // 2048
    }
    int iWq, iWo;
    if (i16[1] == i16[0] + 1) { iWo = i16[0]; iWq = i16[1]; }
    else                      { iWq = i16[0]; iWo = i16[1]; }
    const int iWk = i4[0];
    const int iWv = i4[1];

    const float* hs  = (const float*)d_in[iHS];
    const int*   pos = (const int*)d_in[iPOS];
    const float* Wq  = (const float*)d_in[iWq];
    const float* Wk  = (const float*)d_in[iWk];
    const float* Wv  = (const float*)d_in[iWv];
    const float* Wo  = (const float*)d_in[iWo];
    float* out = (float*)d_out;

    float *Q, *K, *V, *A;
    cudaGetSymbolAddress((void**)&Q, g_Q);
    cudaGetSymbolAddress((void**)&K, g_K);
    cudaGetSymbolAddress((void**)&V, g_V);
    cudaGetSymbolAddress((void**)&A, g_A);

    __nv_bfloat16 *hsh, *hsl, *Wqh, *Wql, *Wkh, *Wkl, *Wvh, *Wvl, *Woh, *Wol, *Ahh, *Ahl;
    cudaGetSymbolAddress((void**)&hsh, g_hsh);
    cudaGetSymbolAddress((void**)&hsl, g_hsl);
    cudaGetSymbolAddress((void**)&Wqh, g_Wqh);
    cudaGetSymbolAddress((void**)&Wql, g_Wql);
    cudaGetSymbolAddress((void**)&Wkh, g_Wkh);
    cudaGetSymbolAddress((void**)&Wkl, g_Wkl);
    cudaGetSymbolAddress((void**)&Wvh, g_Wvh);
    cudaGetSymbolAddress((void**)&Wvl, g_Wvl);
    cudaGetSymbolAddress((void**)&Woh, g_Woh);
    cudaGetSymbolAddress((void**)&Wol, g_Wol);
    cudaGetSymbolAddress((void**)&Ahh, g_Ahh);
    cudaGetSymbolAddress((void**)&Ahl, g_Ahl);

    // ---- pre-split all GEMM operands into bf16 hi/lo ----
    {
        int n;
        n = 2048 * 4096 / 4; split_fp32<<<(n + 255) / 256, 256>>>(hs, hsh, hsl, n);
        n = 4096 * 4096 / 4; split_fp32<<<(n + 255) / 256, 256>>>(Wq, Wqh, Wql, n);
        n = 4096 * 1024 / 4; split_fp32<<<(n + 255) / 256, 256>>>(Wk, Wkh, Wkl, n);
        n = 4096 * 1024 / 4; split_fp32<<<(n + 255) / 256, 256>>>(Wv, Wvh, Wvl, n);
        n = 4096 * 4096 / 4; split_fp32<<<(n + 255) / 256, 256>>>(Wo, Woh, Wol, n);
    }

    // QKV projections (tensor-core bf16 GEMM, pre-split operands)
    {
        dim3 gq(4096 / 128, 2048 / 128);
        mma_gemm_bf<<<gq, 256>>>(hsh, hsl, Wqh, Wql, Q, 2048, 4096, 4096);
        dim3 gkv(1024 / 128, 2048 / 128);
        mma_gemm_bf<<<gkv, 256>>>(hsh, hsl, Wkh, Wkl, K, 2048, 1024, 4096);
        mma_gemm_bf<<<gkv, 256>>>(hsh, hsl, Wvh, Wvl, V, 2048, 1024, 4096);
    }

    // RoPE on Q (32 heads) and K (8 heads)
    {
        int totq = 2048 * 32 * 64;
        rope_naive<<<(totq + 255) / 256, 256>>>(Q, pos, 32);
        int totk = 2048 * 8 * 64;
        rope_naive<<<(totk + 255) / 256, 256>>>(K, pos, 8);
    }

    // Attention (4 q-rows per block)
    {
        dim3 ga(512, 32);
        attn_q4<<<ga, 256>>>(Q, K, V, A);
    }

    // Split attention output, then output projection
    {
        int n = 2048 * 4096 / 4;
        split_fp32<<<(n + 255) / 256, 256>>>(A, Ahh, Ahl, n);
        dim3 go(4096 / 128, 2048 / 128);
        mma_gemm_bf<<<go, 256>>>(Ahh, Ahl, Woh, Wol, out, 2048, 4096, 4096);
    }
}